// round 5
// baseline (speedup 1.0000x reference)
#include <cuda_runtime.h>

#define BB 64
#define TT 2048
#define DK 128
#define DV 128

// ---- packed f32x2 helpers (SASS FFMA2 path — PTX-only) ----
__device__ __forceinline__ unsigned long long pk2(float lo, float hi) {
    unsigned long long r;
    asm("mov.b64 %0, {%1,%2};" : "=l"(r) : "f"(lo), "f"(hi));
    return r;
}
__device__ __forceinline__ unsigned long long fma2(unsigned long long a, unsigned long long b, unsigned long long c) {
    unsigned long long d;
    asm("fma.rn.f32x2 %0, %1, %2, %3;" : "=l"(d) : "l"(a), "l"(b), "l"(c));
    return d;
}
__device__ __forceinline__ unsigned long long mul2_(unsigned long long a, unsigned long long b) {
    unsigned long long d;
    asm("mul.rn.f32x2 %0, %1, %2;" : "=l"(d) : "l"(a), "l"(b));
    return d;
}
__device__ __forceinline__ float2 up2(unsigned long long a) {
    float2 f;
    asm("mov.b64 {%0,%1}, %2;" : "=f"(f.x), "=f"(f.y) : "l"(a));
    return f;
}

struct Buf {
    unsigned long long q2[4];  // this warp's 8 q floats (k rows [8w,8w+8)), packed pairwise
    unsigned long long k2[4];  // this warp's 8 k floats
    float2 v2;                 // lane's 2 v columns
};

__global__ void __launch_bounds__(512, 1)
lmm_scan_kernel(const float* __restrict__ q,
                const float* __restrict__ k,
                const float* __restrict__ v,
                const float* __restrict__ alpha,
                const float* __restrict__ rho,
                const float* __restrict__ lam,
                const float* __restrict__ init,
                float* __restrict__ out)
{
    // CTA = (batch, v-half). 16 warps; warp w owns k rows [8w,8w+8) x 64 v cols.
    // Lane owns 8k x 2v = 8 packed regs. No shuffles, no global atomics:
    // partial sums over each warp's 8 k-rows go to smem; every 4 steps one
    // __syncthreads + 16-way add + coalesced STG (double-buffered smem).
    __shared__ float part[2][4][16][64];   // [buf][step-in-block][warp][vcol] = 32 KB

    const int bid   = blockIdx.x;
    const int b     = bid >> 1;
    const int vhalf = bid & 1;
    const int tid   = threadIdx.x;
    const int warp  = tid >> 5;
    const int lane  = tid & 31;
    const int krow  = warp * 8;                 // warp's 8 k rows
    const int vcol  = vhalf * 64 + lane * 2;    // lane's 2 v columns

    // ---- state M[krow..krow+8) x [vcol..vcol+2), packed pairwise along k ----
    unsigned long long M2[4][2];
    {
        const float* ist = init + (size_t)b * DK * DV;
        #pragma unroll
        for (int kp = 0; kp < 4; kp++) {
            const float* r0 = ist + (size_t)(krow + 2 * kp) * DV + vcol;
            const float* r1 = r0 + DV;
            M2[kp][0] = pk2(r0[0], r1[0]);
            M2[kp][1] = pk2(r0[1], r1[1]);
        }
    }

    const size_t bT = (size_t)b * TT;

    auto load = [&](Buf& bf, int t) {
        size_t roff = (bT + (size_t)t) * DK;
        // warp-uniform 32B loads (all lanes same address -> 1 line each)
        const ulonglong2* qp = reinterpret_cast<const ulonglong2*>(q + roff + krow);
        ulonglong2 x = qp[0], y = qp[1];
        bf.q2[0] = x.x; bf.q2[1] = x.y; bf.q2[2] = y.x; bf.q2[3] = y.y;
        const ulonglong2* kp_ = reinterpret_cast<const ulonglong2*>(k + roff + krow);
        x = kp_[0]; y = kp_[1];
        bf.k2[0] = x.x; bf.k2[1] = x.y; bf.k2[2] = y.x; bf.k2[3] = y.y;
        bf.v2 = *reinterpret_cast<const float2*>(v + roff + vcol);
    };

    auto step = [&](const Buf& bf, float sA, float sR, float sL, int ts, int bs) {
        float w = sA * sR;
        unsigned long long l2  = pk2(sL, sL);
        float w0 = w * bf.v2.x, w1 = w * bf.v2.y;
        unsigned long long wv0 = pk2(w0, w0);
        unsigned long long wv1 = pk2(w1, w1);
        unsigned long long racc0, racc1;
        #pragma unroll
        for (int kp = 0; kp < 4; kp++) {
            unsigned long long t0 = mul2_(bf.k2[kp], wv0);      // (w*v0)*k
            M2[kp][0] = fma2(l2, M2[kp][0], t0);                // M = l*M + wv*k
            racc0 = (kp == 0) ? mul2_(bf.q2[0], M2[0][0])       // r += q*M (post-update)
                              : fma2(bf.q2[kp], M2[kp][0], racc0);
            unsigned long long t1 = mul2_(bf.k2[kp], wv1);
            M2[kp][1] = fma2(l2, M2[kp][1], t1);
            racc1 = (kp == 0) ? mul2_(bf.q2[0], M2[0][1])
                              : fma2(bf.q2[kp], M2[kp][1], racc1);
        }
        float r0, r1;
        { float2 u = up2(racc0); r0 = u.x + u.y; }
        { float2 u = up2(racc1); r1 = u.x + u.y; }
        // partial over this warp's 8 k rows -> smem (conflict-free float2)
        *reinterpret_cast<float2*>(&part[bs][ts][warp][lane * 2]) = make_float2(r0, r1);
    };

    Buf buf0, buf1, buf2, buf3;
    load(buf0, 0);
    load(buf1, 1);

    int bs = 0;
    const int rcol  = tid & 63;        // reducer's column
    const int rts   = (tid >> 6) & 3;  // reducer's step-in-block
    float* outbase  = out + vhalf * 64 + rcol;

    for (int tb = 0; tb < TT; tb += 4) {
        float4 sa = *reinterpret_cast<const float4*>(alpha + bT + tb);
        float4 sr = *reinterpret_cast<const float4*>(rho   + bT + tb);
        float4 sl = *reinterpret_cast<const float4*>(lam   + bT + tb);

        load(buf2, tb + 2);
        step(buf0, sa.x, sr.x, sl.x, 0, bs);

        int t3 = tb + 3; if (t3 > TT - 1) t3 = TT - 1;
        load(buf3, t3);
        step(buf1, sa.y, sr.y, sl.y, 1, bs);

        int t4 = tb + 4; if (t4 > TT - 1) t4 = TT - 1;
        load(buf0, t4);
        step(buf2, sa.z, sr.z, sl.z, 2, bs);

        int t5 = tb + 5; if (t5 > TT - 1) t5 = TT - 1;
        load(buf1, t5);
        step(buf3, sa.w, sr.w, sl.w, 3, bs);

        __syncthreads();   // block's partials visible; also protects buffer reuse

        if (tid < 256) {
            // 16-way add across warps for (t = tb + rts, col = rcol)
            float s = 0.f;
            #pragma unroll
            for (int w8 = 0; w8 < 16; w8++)
                s += part[bs][rts][w8][rcol];
            outbase[(bT + (size_t)(tb + rts)) * DV] = s;
        }
        bs ^= 1;
    }
}

extern "C" void kernel_launch(void* const* d_in, const int* in_sizes, int n_in,
                              void* d_out, int out_size)
{
    const float* q     = (const float*)d_in[0];
    const float* k     = (const float*)d_in[1];
    const float* v     = (const float*)d_in[2];
    const float* alpha = (const float*)d_in[3];
    const float* rho   = (const float*)d_in[4];
    const float* lam   = (const float*)d_in[5];
    const float* init  = (const float*)d_in[6];
    float* out = (float*)d_out;
    (void)in_sizes; (void)n_in; (void)out_size;

    lmm_scan_kernel<<<BB * 2, 512>>>(q, k, v, alpha, rho, lam, init, out);
}